// round 15
// baseline (speedup 1.0000x reference)
#include <cuda_runtime.h>

#define NN 100000
#define NE 1600000
#define D 48
#define NCONVS 6
#define NG 1000

#define EPC 256     // edges per CTA (128 threads: 64 edge-quads x 2 column-halves)
#define XSTRIDE 49  // padded x row stride in floats (odd -> conflict-free scalar LDS)

#define SCAN_BLK 1024
#define NSCAN_BLKS ((NN + SCAN_BLK - 1) / SCAN_BLK)   // 98

typedef unsigned long long u64;

// Scratch state (no allocation allowed).
__device__ float4 g_h[NN * 12];
__device__ float4 g_agg[NN * 12];
// counting-sort scratch
__device__ int g_cnt[NN];
__device__ int g_scan[NN];
__device__ int g_bsum[NSCAN_BLKS];
__device__ int g_woff[NN];
__device__ int g_ssrc[NE];
__device__ int g_sdst[NE];

// Per-layer weights in constant memory (copied per layer via memcpy nodes).
// Layout: [0:2304) w1, [2304:4608) w2, [4608:4656) b1, [4656:4704) b2.
__constant__ float c_mw[4704];   // message MLP (edge kernel)
__constant__ float c_uw[4704];   // update MLP (node kernel)

// ---------- packed f32x2 helpers ----------
__device__ __forceinline__ u64 fma2(u64 a, u64 b, u64 c) {
    u64 d;
    asm("fma.rn.f32x2 %0, %1, %2, %3;" : "=l"(d) : "l"(a), "l"(b), "l"(c));
    return d;
}
__device__ __forceinline__ u64 add2(u64 a, u64 b) {
    u64 d;
    asm("add.rn.f32x2 %0, %1, %2;" : "=l"(d) : "l"(a), "l"(b));
    return d;
}
__device__ __forceinline__ u64 pack2(float lo, float hi) {
    u64 r;
    asm("mov.b64 %0, {%1, %2};" : "=l"(r) : "f"(lo), "f"(hi));
    return r;
}
__device__ __forceinline__ float2 unpack2(u64 v) {
    float2 f;
    asm("mov.b64 {%0, %1}, %2;" : "=f"(f.x), "=f"(f.y) : "l"(v));
    return f;
}

// ---------- counting sort by dst ----------
__global__ void zero_cnt_kernel() {
    int i = blockIdx.x * blockDim.x + threadIdx.x;
    if (i < NN) g_cnt[i] = 0;
}
__global__ void hist_kernel(const int* __restrict__ edge) {
    int e = blockIdx.x * blockDim.x + threadIdx.x;
    if (e < NE) atomicAdd(&g_cnt[edge[NE + e]], 1);
}
__global__ void scan1_kernel() {
    __shared__ int sh[SCAN_BLK];
    int tid = threadIdx.x;
    int i = blockIdx.x * SCAN_BLK + tid;
    int v = (i < NN) ? g_cnt[i] : 0;
    sh[tid] = v;
    __syncthreads();
#pragma unroll
    for (int o = 1; o < SCAN_BLK; o <<= 1) {
        int t = (tid >= o) ? sh[tid - o] : 0;
        __syncthreads();
        sh[tid] += t;
        __syncthreads();
    }
    if (i < NN) g_scan[i] = sh[tid];
    if (tid == SCAN_BLK - 1) g_bsum[blockIdx.x] = sh[tid];
}
__global__ void scan2_kernel() {
    if (threadIdx.x == 0 && blockIdx.x == 0) {
        int acc = 0;
        for (int b = 0; b < NSCAN_BLKS; b++) {
            int t = g_bsum[b];
            g_bsum[b] = acc;
            acc += t;
        }
    }
}
__global__ void scan3_kernel() {
    int i = blockIdx.x * blockDim.x + threadIdx.x;
    if (i < NN) g_woff[i] = g_scan[i] - g_cnt[i] + g_bsum[i / SCAN_BLK];
}
__global__ void scatter_sort_kernel(const int* __restrict__ edge) {
    int e = blockIdx.x * blockDim.x + threadIdx.x;
    if (e >= NE) return;
    int d = edge[NE + e];
    int pos = atomicAdd(&g_woff[d], 1);
    g_ssrc[pos] = edge[e];
    g_sdst[pos] = d;
}

// ---------- quad-edge half-width GEMM: x from SMEM, W from __constant__ ----------
// 24 output cols (coff selects half) for 4 edges; each weight LDC.128 reused 4x.
__device__ __forceinline__ void gemm48_quad_c(const float* __restrict__ x0,
                                              const float* __restrict__ x1,
                                              const float* __restrict__ x2,
                                              const float* __restrict__ x3,
                                              u64 acc[4][12],
                                              const float (&cw)[4704],
                                              int wofs, int bofs, int coff) {
#pragma unroll
    for (int j = 0; j < 12; j++) {
        u64 b = *reinterpret_cast<const u64*>(&cw[bofs + coff + 2 * j]);
        acc[0][j] = b;
        acc[1][j] = b;
        acc[2][j] = b;
        acc[3][j] = b;
    }
#pragma unroll 4
    for (int k = 0; k < D; k++) {
        u64 xk0 = pack2(x0[k], x0[k]);
        u64 xk1 = pack2(x1[k], x1[k]);
        u64 xk2 = pack2(x2[k], x2[k]);
        u64 xk3 = pack2(x3[k], x3[k]);
        const ulonglong2* wr = reinterpret_cast<const ulonglong2*>(&cw[wofs + k * D + coff]);
#pragma unroll
        for (int jj = 0; jj < 6; jj++) {
            ulonglong2 w = wr[jj];
            acc[0][2 * jj]     = fma2(xk0, w.x, acc[0][2 * jj]);
            acc[0][2 * jj + 1] = fma2(xk0, w.y, acc[0][2 * jj + 1]);
            acc[1][2 * jj]     = fma2(xk1, w.x, acc[1][2 * jj]);
            acc[1][2 * jj + 1] = fma2(xk1, w.y, acc[1][2 * jj + 1]);
            acc[2][2 * jj]     = fma2(xk2, w.x, acc[2][2 * jj]);
            acc[2][2 * jj + 1] = fma2(xk2, w.y, acc[2][2 * jj + 1]);
            acc[3][2 * jj]     = fma2(xk3, w.x, acc[3][2 * jj]);
            acc[3][2 * jj + 1] = fma2(xk3, w.y, acc[3][2 * jj + 1]);
        }
    }
}

// relu 24-wide accumulator half back into smem row (at col offset already applied)
__device__ __forceinline__ void relu_wb24(float* xrow, const u64 a[12]) {
#pragma unroll
    for (int j = 0; j < 12; j++) {
        float2 v = unpack2(a[j]);
        xrow[2 * j]     = fmaxf(v.x, 0.f);
        xrow[2 * j + 1] = fmaxf(v.y, 0.f);
    }
}

// ---------- dual-row full-width GEMM (update kernel, constant weights) ----------
__device__ __forceinline__ void gemm48_dual_c(const float* __restrict__ x0,
                                              const float* __restrict__ x1,
                                              u64 acc0[24], u64 acc1[24],
                                              const float (&cw)[4704],
                                              int wofs, int bofs) {
#pragma unroll
    for (int j = 0; j < 24; j++) {
        u64 b = *reinterpret_cast<const u64*>(&cw[bofs + 2 * j]);
        acc0[j] = b;
        acc1[j] = b;
    }
#pragma unroll 4
    for (int k = 0; k < D; k++) {
        float a0 = x0[k];
        float a1 = x1[k];
        u64 xk0 = pack2(a0, a0);
        u64 xk1 = pack2(a1, a1);
        const ulonglong2* wr = reinterpret_cast<const ulonglong2*>(&cw[wofs + k * D]);
#pragma unroll
        for (int jj = 0; jj < 12; jj++) {
            ulonglong2 w = wr[jj];
            acc0[2 * jj]     = fma2(xk0, w.x, acc0[2 * jj]);
            acc0[2 * jj + 1] = fma2(xk0, w.y, acc0[2 * jj + 1]);
            acc1[2 * jj]     = fma2(xk1, w.x, acc1[2 * jj]);
            acc1[2 * jj + 1] = fma2(xk1, w.y, acc1[2 * jj + 1]);
        }
    }
}

__device__ __forceinline__ void relu_writeback(float* x, const u64 a[24]) {
#pragma unroll
    for (int j = 0; j < 24; j++) {
        float2 v = unpack2(a[j]);
        x[2 * j]     = fmaxf(v.x, 0.f);
        x[2 * j + 1] = fmaxf(v.y, 0.f);
    }
}

// ---------- single-row half GEMM (readout, smem weights) ----------
__device__ __forceinline__ void gemm48_half(const float x[D], u64 acc[12],
                                            const float* __restrict__ ws,
                                            const float* __restrict__ bs) {
#pragma unroll
    for (int j = 0; j < 12; j++) acc[j] = *(const u64*)(bs + 2 * j);
#pragma unroll 4
    for (int k = 0; k < D; k++) {
        u64 xk = pack2(x[k], x[k]);
        const ulonglong2* wr = (const ulonglong2*)(ws + k * D);
#pragma unroll
        for (int jj = 0; jj < 6; jj++) {
            ulonglong2 w = wr[jj];
            acc[2 * jj]     = fma2(xk, w.x, acc[2 * jj]);
            acc[2 * jj + 1] = fma2(xk, w.y, acc[2 * jj + 1]);
        }
    }
}

// ---------- kernels ----------

__global__ void embed_kernel(const int* __restrict__ an, const float4* __restrict__ emb4) {
    int i = blockIdx.x * blockDim.x + threadIdx.x;
    if (i >= NN * 12) return;
    int node = i / 12;
    int v = i - node * 12;
    g_h[i] = emb4[an[node] * 12 + v];
    g_agg[i] = make_float4(0.f, 0.f, 0.f, 0.f);
}

// scatter 24 floats (one output half) into agg at given base (half offset applied)
__device__ __forceinline__ void scatter24(float* aggp, const u64 a[12]) {
#pragma unroll
    for (int v = 0; v < 3; v++) {
        float2 p0 = unpack2(a[4 * v + 0]);
        float2 p1 = unpack2(a[4 * v + 1]);
        float2 p2 = unpack2(a[4 * v + 2]);
        float2 p3 = unpack2(a[4 * v + 3]);
        asm volatile("red.global.add.v4.f32 [%0], {%1, %2, %3, %4};"
                     :: "l"(aggp + 8 * v), "f"(p0.x), "f"(p0.y), "f"(p1.x), "f"(p1.y) : "memory");
        asm volatile("red.global.add.v4.f32 [%0], {%1, %2, %3, %4};"
                     :: "l"(aggp + 8 * v + 4), "f"(p2.x), "f"(p2.y), "f"(p3.x), "f"(p3.y) : "memory");
    }
}

// SMEM (floats): [0:256) esrc ints, [256:512) edst ints, [512: +256*49) x rows.
// Edge el -> row ((el&3)<<6)+(el>>2): phase-2 thread (q = tid&63) owns rows
// q, 64+q, 128+q, 192+q = edges 4q..4q+3 (consecutive after dst-sort).
#define OFF_X 512
#define EDGE_SMEM_FLOATS (OFF_X + EPC * XSTRIDE)   // 13056 floats ~ 52 KB
#define UPD_SMEM_FLOATS  (EPC * XSTRIDE)           // 12544 floats ~ 50 KB

__global__ __launch_bounds__(128, 3) void edge_kernel(int unused) {
    extern __shared__ __align__(16) float s[];
    int* esrc = (int*)s;
    int* edst = (int*)(s + 256);
    float* xs = s + OFF_X;
    int tid = threadIdx.x;

    // Stage edge ids coalescedly.
    int e_base = blockIdx.x * EPC;
#pragma unroll
    for (int i = tid; i < EPC; i += 128) {
        esrc[i] = g_ssrc[e_base + i];
        edst[i] = g_sdst[e_base + i];
    }
    __syncthreads();

    // Phase 1: coalesced gather, 4 lanes per edge (ids via broadcast LDS).
#pragma unroll
    for (int it = 0; it < 8; it++) {
        int idx = it * 128 + tid;      // 0..1023
        int el = idx >> 2;             // local edge 0..255
        int ch = idx & 3;              // chunk 0..3
        int sn = esrc[el];
        int dn = edst[el];
        const float4* hs = (const float4*)&g_h[sn * 12] + ch * 3;
        const float4* hd = (const float4*)&g_h[dn * 12] + ch * 3;
        int row = ((el & 3) << 6) + (el >> 2);
        float* xrow = xs + row * XSTRIDE + ch * 12;
#pragma unroll
        for (int i = 0; i < 3; i++) {
            float4 a = hs[i];
            float4 b = hd[i];
            xrow[4 * i + 0] = a.x * b.x;
            xrow[4 * i + 1] = a.y * b.y;
            xrow[4 * i + 2] = a.z * b.z;
            xrow[4 * i + 3] = a.w * b.w;
        }
    }
    __syncthreads();

    // Phase 2: quad edges 4q..4q+3, half output columns per thread.
    int q = tid & 63;
    int coff = (tid >> 6) * 24;       // column half offset: 0 or 24
    float* xr0 = xs + q * XSTRIDE;
    float* xr1 = xs + (64 + q) * XSTRIDE;
    float* xr2 = xs + (128 + q) * XSTRIDE;
    float* xr3 = xs + (192 + q) * XSTRIDE;

    {
        u64 acc[4][12];
        gemm48_quad_c(xr0, xr1, xr2, xr3, acc, c_mw, 0, 4608, coff);
        // RACE FIX: every thread must finish READING x (GEMM1) before any
        // thread overwrites the shared rows with relu(hidden). The partner
        // half lives in a different warp, so a barrier is required here.
        __syncthreads();
        relu_wb24(xr0 + coff, acc[0]);
        relu_wb24(xr1 + coff, acc[1]);
        relu_wb24(xr2 + coff, acc[2]);
        relu_wb24(xr3 + coff, acc[3]);
    }
    __syncthreads();   // hidden fully written (both halves) before GEMM2 reads

    u64 acc[4][12];
    gemm48_quad_c(xr0, xr1, xr2, xr3, acc, c_mw, 2304, 4656, coff);

    // Scatter with run-merge over 4 consecutive dst-sorted edges.
    int e0 = 4 * q;
    int d0 = edst[e0 + 0];
    int d1 = edst[e0 + 1];
    int d2 = edst[e0 + 2];
    int d3 = edst[e0 + 3];
    float* aggbase = (float*)g_agg;

    u64 sum[12];
#pragma unroll
    for (int j = 0; j < 12; j++) sum[j] = acc[0][j];
    int cur = d0;
#pragma unroll
    for (int i = 1; i < 4; i++) {
        int di = (i == 1) ? d1 : (i == 2) ? d2 : d3;
        if (di == cur) {
#pragma unroll
            for (int j = 0; j < 12; j++) sum[j] = add2(sum[j], acc[i][j]);
        } else {
            scatter24(aggbase + cur * D + coff, sum);
            cur = di;
#pragma unroll
            for (int j = 0; j < 12; j++) sum[j] = acc[i][j];
        }
    }
    scatter24(aggbase + cur * D + coff, sum);
}

// Dual-node update kernel: constant weights, x staged in smem (R13 form —
// rows are NOT shared across threads here, so in-place relu is race-free).
__global__ __launch_bounds__(128, 3) void update_kernel(int unused) {
    extern __shared__ __align__(16) float s[];
    float* xs = s;
    int tid = threadIdx.x;

    int n_base = blockIdx.x * 256;
    const float4 z = make_float4(0.f, 0.f, 0.f, 0.f);
#pragma unroll
    for (int it = 0; it < 8; it++) {
        int idx = it * 128 + tid;
        int nl = idx >> 2;
        int ch = idx & 3;
        int n = n_base + nl;
        if (n < NN) {
            float4* ap = &g_agg[n * 12] + ch * 3;
            int row = ((nl & 1) << 7) + (nl >> 1);
            float* xrow = xs + row * XSTRIDE + ch * 12;
#pragma unroll
            for (int i = 0; i < 3; i++) {
                float4 a = ap[i];
                xrow[4 * i + 0] = a.x;
                xrow[4 * i + 1] = a.y;
                xrow[4 * i + 2] = a.z;
                xrow[4 * i + 3] = a.w;
                ap[i] = z;  // reset for next layer's scatter
            }
        }
    }
    __syncthreads();

    int n0 = n_base + 2 * tid;
    if (n0 >= NN) return;
    int n1 = n0 + 1;

    float* x0 = xs + tid * XSTRIDE;
    float* x1 = xs + (tid + 128) * XSTRIDE;

    {
        u64 a0[24], a1[24];
        gemm48_dual_c(x0, x1, a0, a1, c_uw, 0, 4608);
        relu_writeback(x0, a0);
        relu_writeback(x1, a1);
    }

    u64 a0[24], a1[24];
    gemm48_dual_c(x0, x1, a0, a1, c_uw, 2304, 4656);

    {
        float4* hp = &g_h[n0 * 12];
#pragma unroll
        for (int v = 0; v < 12; v++) {
            float2 p0 = unpack2(a0[2 * v]);
            float2 p1 = unpack2(a0[2 * v + 1]);
            float4 h = hp[v];
            h.x += p0.x; h.y += p0.y; h.z += p1.x; h.w += p1.y;
            hp[v] = h;
        }
    }
    if (n1 < NN) {
        float4* hp = &g_h[n1 * 12];
#pragma unroll
        for (int v = 0; v < 12; v++) {
            float2 p0 = unpack2(a1[2 * v]);
            float2 p1 = unpack2(a1[2 * v + 1]);
            float4 h = hp[v];
            h.x += p0.x; h.y += p0.y; h.z += p1.x; h.w += p1.y;
            hp[v] = h;
        }
    }
}

__global__ __launch_bounds__(256, 2) void readout_kernel(
    const int* __restrict__ gid,
    const float* __restrict__ rw1, const float* __restrict__ rb1,
    const float* __restrict__ rw2, const float* __restrict__ rb2,
    float* __restrict__ out) {
    __shared__ __align__(16) float s[2402];
    for (int i = threadIdx.x; i < D * D; i += blockDim.x) s[i] = rw1[i];
    if (threadIdx.x < D) {
        s[2304 + threadIdx.x] = rb1[threadIdx.x];
        s[2352 + threadIdx.x] = rw2[threadIdx.x];
    }
    if (threadIdx.x == 0) s[2400] = rb2[0];
    __syncthreads();

    int n = blockIdx.x * 256 + threadIdx.x;
    if (n >= NN) return;

    const float4* hp = &g_h[n * 12];
    float x[D];
#pragma unroll
    for (int v = 0; v < 12; v++) {
        float4 a = hp[v];
        x[4 * v + 0] = a.x;
        x[4 * v + 1] = a.y;
        x[4 * v + 2] = a.z;
        x[4 * v + 3] = a.w;
    }

    float y = s[2400];
#pragma unroll 1
    for (int half = 0; half < 2; half++) {
        u64 acc[12];
        gemm48_half(x, acc, s + half * 24, s + 2304 + half * 24);
#pragma unroll
        for (int j = 0; j < 12; j++) {
            float2 v = unpack2(acc[j]);
            y += fmaxf(v.x, 0.f) * s[2352 + half * 24 + 2 * j];
            y += fmaxf(v.y, 0.f) * s[2352 + half * 24 + 2 * j + 1];
        }
    }

    atomicAdd(&out[gid[n]], y);
}

extern "C" void kernel_launch(void* const* d_in, const int* in_sizes, int n_in,
                              void* d_out, int out_size) {
    const int*   an   = (const int*)d_in[0];
    const int*   edge = (const int*)d_in[1];
    const int*   gid  = (const int*)d_in[2];
    const float* emb  = (const float*)d_in[3];
    const float* mw1  = (const float*)d_in[4];
    const float* mb1  = (const float*)d_in[5];
    const float* mw2  = (const float*)d_in[6];
    const float* mb2  = (const float*)d_in[7];
    const float* uw1  = (const float*)d_in[8];
    const float* ub1  = (const float*)d_in[9];
    const float* uw2  = (const float*)d_in[10];
    const float* ub2  = (const float*)d_in[11];
    const float* rw1  = (const float*)d_in[12];
    const float* rb1  = (const float*)d_in[13];
    const float* rw2  = (const float*)d_in[14];
    const float* rb2  = (const float*)d_in[15];
    float* out = (float*)d_out;

    const int edge_smem = EDGE_SMEM_FLOATS * (int)sizeof(float);  // ~52 KB
    const int upd_smem  = UPD_SMEM_FLOATS * (int)sizeof(float);   // ~50 KB
    cudaFuncSetAttribute(edge_kernel, cudaFuncAttributeMaxDynamicSharedMemorySize, edge_smem);
    cudaFuncSetAttribute(update_kernel, cudaFuncAttributeMaxDynamicSharedMemorySize, upd_smem);

    // counting sort of edges by dst (edge list constant across layers)
    zero_cnt_kernel<<<(NN + 255) / 256, 256>>>();
    hist_kernel<<<(NE + 255) / 256, 256>>>(edge);
    scan1_kernel<<<NSCAN_BLKS, SCAN_BLK>>>();
    scan2_kernel<<<1, 32>>>();
    scan3_kernel<<<(NN + 255) / 256, 256>>>();
    scatter_sort_kernel<<<(NE + 255) / 256, 256>>>(edge);

    embed_kernel<<<(NN * 12 + 255) / 256, 256>>>(an, (const float4*)emb);

    for (int l = 0; l < NCONVS; l++) {
        cudaMemcpyToSymbolAsync(c_mw, mw1 + l * 2304, 2304 * sizeof(float), 0, cudaMemcpyDeviceToDevice);
        cudaMemcpyToSymbolAsync(c_mw, mw2 + l * 2304, 2304 * sizeof(float), 2304 * sizeof(float), cudaMemcpyDeviceToDevice);
        cudaMemcpyToSymbolAsync(c_mw, mb1 + l * D, D * sizeof(float), 4608 * sizeof(float), cudaMemcpyDeviceToDevice);
        cudaMemcpyToSymbolAsync(c_mw, mb2 + l * D, D * sizeof(float), 4656 * sizeof(float), cudaMemcpyDeviceToDevice);
        edge_kernel<<<NE / EPC, 128, edge_smem>>>(0);

        cudaMemcpyToSymbolAsync(c_uw, uw1 + l * 2304, 2304 * sizeof(float), 0, cudaMemcpyDeviceToDevice);
        cudaMemcpyToSymbolAsync(c_uw, uw2 + l * 2304, 2304 * sizeof(float), 2304 * sizeof(float), cudaMemcpyDeviceToDevice);
        cudaMemcpyToSymbolAsync(c_uw, ub1 + l * D, D * sizeof(float), 4608 * sizeof(float), cudaMemcpyDeviceToDevice);
        cudaMemcpyToSymbolAsync(c_uw, ub2 + l * D, D * sizeof(float), 4656 * sizeof(float), cudaMemcpyDeviceToDevice);
        update_kernel<<<(NN + 255) / 256, 128, upd_smem>>>(0);
    }

    cudaMemsetAsync(out, 0, NG * sizeof(float));
    readout_kernel<<<(NN + 255) / 256, 256>>>(gid, rw1, rb1, rw2, rb2, out);
}

// round 16
// speedup vs baseline: 1.2090x; 1.2090x over previous
#include <cuda_runtime.h>

#define NN 100000
#define NE 1600000
#define D 48
#define NCONVS 6
#define NG 1000

#define EPC 256     // edges per CTA (128 threads, 2 consecutive edges/thread)
#define XSTRIDE 49  // padded x row stride in floats (odd -> conflict-free scalar LDS)

#define SCAN_BLK 1024
#define NSCAN_BLKS ((NN + SCAN_BLK - 1) / SCAN_BLK)   // 98

typedef unsigned long long u64;

// Scratch state (no allocation allowed).
__device__ float4 g_h[NN * 12];
__device__ float4 g_agg[NN * 12];
// counting-sort scratch
__device__ int g_cnt[NN];
__device__ int g_scan[NN];
__device__ int g_bsum[NSCAN_BLKS];
__device__ int g_woff[NN];
__device__ int g_ssrc[NE];
__device__ int g_sdst[NE];
// packed per-layer weight staging: [l][0:2304) w1, [2304:4608) w2,
// [4608:4656) b1, [4656:4704) b2
__device__ float g_packm[NCONVS * 4704];
__device__ float g_packu[NCONVS * 4704];

// Per-layer weights in constant memory (one memcpy node per kernel per layer).
__constant__ float c_mw[4704];   // message MLP (edge kernel)
__constant__ float c_uw[4704];   // update MLP (node kernel)

// ---------- packed f32x2 helpers ----------
__device__ __forceinline__ u64 fma2(u64 a, u64 b, u64 c) {
    u64 d;
    asm("fma.rn.f32x2 %0, %1, %2, %3;" : "=l"(d) : "l"(a), "l"(b), "l"(c));
    return d;
}
__device__ __forceinline__ u64 add2(u64 a, u64 b) {
    u64 d;
    asm("add.rn.f32x2 %0, %1, %2;" : "=l"(d) : "l"(a), "l"(b));
    return d;
}
__device__ __forceinline__ u64 pack2(float lo, float hi) {
    u64 r;
    asm("mov.b64 %0, {%1, %2};" : "=l"(r) : "f"(lo), "f"(hi));
    return r;
}
__device__ __forceinline__ float2 unpack2(u64 v) {
    float2 f;
    asm("mov.b64 {%0, %1}, %2;" : "=f"(f.x), "=f"(f.y) : "l"(v));
    return f;
}

// ---------- weight packing ----------
__global__ void pack_weights_kernel(const float* __restrict__ mw1, const float* __restrict__ mb1,
                                    const float* __restrict__ mw2, const float* __restrict__ mb2,
                                    const float* __restrict__ uw1, const float* __restrict__ ub1,
                                    const float* __restrict__ uw2, const float* __restrict__ ub2) {
    int i = blockIdx.x * blockDim.x + threadIdx.x;   // over NCONVS*4704
    if (i >= NCONVS * 4704) return;
    int l = i / 4704;
    int o = i - l * 4704;
    float m, u;
    if (o < 2304) {
        m = mw1[l * 2304 + o];
        u = uw1[l * 2304 + o];
    } else if (o < 4608) {
        m = mw2[l * 2304 + o - 2304];
        u = uw2[l * 2304 + o - 2304];
    } else if (o < 4656) {
        m = mb1[l * D + o - 4608];
        u = ub1[l * D + o - 4608];
    } else {
        m = mb2[l * D + o - 4656];
        u = ub2[l * D + o - 4656];
    }
    g_packm[i] = m;
    g_packu[i] = u;
}

// ---------- counting sort by dst ----------
__global__ void zero_cnt_kernel() {
    int i = blockIdx.x * blockDim.x + threadIdx.x;
    if (i < NN) g_cnt[i] = 0;
}
__global__ void hist_kernel(const int* __restrict__ edge) {
    int e = blockIdx.x * blockDim.x + threadIdx.x;
    if (e < NE) atomicAdd(&g_cnt[edge[NE + e]], 1);
}
__global__ void scan1_kernel() {
    __shared__ int sh[SCAN_BLK];
    int tid = threadIdx.x;
    int i = blockIdx.x * SCAN_BLK + tid;
    int v = (i < NN) ? g_cnt[i] : 0;
    sh[tid] = v;
    __syncthreads();
#pragma unroll
    for (int o = 1; o < SCAN_BLK; o <<= 1) {
        int t = (tid >= o) ? sh[tid - o] : 0;
        __syncthreads();
        sh[tid] += t;
        __syncthreads();
    }
    if (i < NN) g_scan[i] = sh[tid];
    if (tid == SCAN_BLK - 1) g_bsum[blockIdx.x] = sh[tid];
}
__global__ void scan2_kernel() {
    if (threadIdx.x == 0 && blockIdx.x == 0) {
        int acc = 0;
        for (int b = 0; b < NSCAN_BLKS; b++) {
            int t = g_bsum[b];
            g_bsum[b] = acc;
            acc += t;
        }
    }
}
__global__ void scan3_kernel() {
    int i = blockIdx.x * blockDim.x + threadIdx.x;
    if (i < NN) g_woff[i] = g_scan[i] - g_cnt[i] + g_bsum[i / SCAN_BLK];
}
__global__ void scatter_sort_kernel(const int* __restrict__ edge) {
    int e = blockIdx.x * blockDim.x + threadIdx.x;
    if (e >= NE) return;
    int d = edge[NE + e];
    int pos = atomicAdd(&g_woff[d], 1);
    g_ssrc[pos] = edge[e];
    g_sdst[pos] = d;
}

// ---------- dual-row full-width GEMM: x from SMEM, W from __constant__ ----------
__device__ __forceinline__ void gemm48_dual_c(const float* __restrict__ x0,
                                              const float* __restrict__ x1,
                                              u64 acc0[24], u64 acc1[24],
                                              const float (&cw)[4704],
                                              int wofs, int bofs) {
#pragma unroll
    for (int j = 0; j < 24; j++) {
        u64 b = *reinterpret_cast<const u64*>(&cw[bofs + 2 * j]);
        acc0[j] = b;
        acc1[j] = b;
    }
#pragma unroll 4
    for (int k = 0; k < D; k++) {
        float a0 = x0[k];
        float a1 = x1[k];
        u64 xk0 = pack2(a0, a0);
        u64 xk1 = pack2(a1, a1);
        const ulonglong2* wr = reinterpret_cast<const ulonglong2*>(&cw[wofs + k * D]);
#pragma unroll
        for (int jj = 0; jj < 12; jj++) {
            ulonglong2 w = wr[jj];
            acc0[2 * jj]     = fma2(xk0, w.x, acc0[2 * jj]);
            acc0[2 * jj + 1] = fma2(xk0, w.y, acc0[2 * jj + 1]);
            acc1[2 * jj]     = fma2(xk1, w.x, acc1[2 * jj]);
            acc1[2 * jj + 1] = fma2(xk1, w.y, acc1[2 * jj + 1]);
        }
    }
}

// relu accumulators back into own smem x rows (same-thread, no sync needed)
__device__ __forceinline__ void relu_writeback(float* x, const u64 a[24]) {
#pragma unroll
    for (int j = 0; j < 24; j++) {
        float2 v = unpack2(a[j]);
        x[2 * j]     = fmaxf(v.x, 0.f);
        x[2 * j + 1] = fmaxf(v.y, 0.f);
    }
}

// ---------- single-row half GEMM (readout, smem weights) ----------
__device__ __forceinline__ void gemm48_half(const float x[D], u64 acc[12],
                                            const float* __restrict__ ws,
                                            const float* __restrict__ bs) {
#pragma unroll
    for (int j = 0; j < 12; j++) acc[j] = *(const u64*)(bs + 2 * j);
#pragma unroll 4
    for (int k = 0; k < D; k++) {
        u64 xk = pack2(x[k], x[k]);
        const ulonglong2* wr = (const ulonglong2*)(ws + k * D);
#pragma unroll
        for (int jj = 0; jj < 6; jj++) {
            ulonglong2 w = wr[jj];
            acc[2 * jj]     = fma2(xk, w.x, acc[2 * jj]);
            acc[2 * jj + 1] = fma2(xk, w.y, acc[2 * jj + 1]);
        }
    }
}

// ---------- kernels ----------

__global__ void embed_kernel(const int* __restrict__ an, const float4* __restrict__ emb4) {
    int i = blockIdx.x * blockDim.x + threadIdx.x;
    if (i >= NN * 12) return;
    int node = i / 12;
    int v = i - node * 12;
    g_h[i] = emb4[an[node] * 12 + v];
    g_agg[i] = make_float4(0.f, 0.f, 0.f, 0.f);
}

__device__ __forceinline__ void scatter48(float* aggp, const u64 a[24]) {
#pragma unroll
    for (int v = 0; v < 6; v++) {
        float2 p0 = unpack2(a[4 * v + 0]);
        float2 p1 = unpack2(a[4 * v + 1]);
        float2 p2 = unpack2(a[4 * v + 2]);
        float2 p3 = unpack2(a[4 * v + 3]);
        asm volatile("red.global.add.v4.f32 [%0], {%1, %2, %3, %4};"
                     :: "l"(aggp + 8 * v), "f"(p0.x), "f"(p0.y), "f"(p1.x), "f"(p1.y) : "memory");
        asm volatile("red.global.add.v4.f32 [%0], {%1, %2, %3, %4};"
                     :: "l"(aggp + 8 * v + 4), "f"(p2.x), "f"(p2.y), "f"(p3.x), "f"(p3.y) : "memory");
    }
}

// SMEM (floats): [0:256) esrc ints, [256:512) edst ints, [512: +256*49) x rows.
// Edge el -> row ((el&1)<<7)+(el>>1): phase-2 thread t owns rows t, t+128
// = edges 2t, 2t+1 (consecutive after dst-sort).
#define OFF_X 512
#define EDGE_SMEM_FLOATS (OFF_X + EPC * XSTRIDE)   // 13056 floats ~ 52 KB
#define UPD_SMEM_FLOATS  (EPC * XSTRIDE)           // 12544 floats ~ 50 KB

__global__ __launch_bounds__(128, 3) void edge_kernel(int unused) {
    extern __shared__ __align__(16) float s[];
    int* esrc = (int*)s;
    int* edst = (int*)(s + 256);
    float* xs = s + OFF_X;
    int tid = threadIdx.x;

    // Stage edge ids coalescedly.
    int e_base = blockIdx.x * EPC;
#pragma unroll
    for (int i = tid; i < EPC; i += 128) {
        esrc[i] = g_ssrc[e_base + i];
        edst[i] = g_sdst[e_base + i];
    }
    __syncthreads();

    // Phase 1: coalesced gather, 4 lanes per edge (ids via broadcast LDS).
#pragma unroll
    for (int it = 0; it < 8; it++) {
        int idx = it * 128 + tid;      // 0..1023
        int el = idx >> 2;             // local edge 0..255
        int ch = idx & 3;              // chunk 0..3
        int sn = esrc[el];
        int dn = edst[el];
        const float4* hs = (const float4*)&g_h[sn * 12] + ch * 3;
        const float4* hd = (const float4*)&g_h[dn * 12] + ch * 3;
        int row = ((el & 1) << 7) + (el >> 1);
        float* xrow = xs + row * XSTRIDE + ch * 12;
#pragma unroll
        for (int i = 0; i < 3; i++) {
            float4 a = hs[i];
            float4 b = hd[i];
            xrow[4 * i + 0] = a.x * b.x;
            xrow[4 * i + 1] = a.y * b.y;
            xrow[4 * i + 2] = a.z * b.z;
            xrow[4 * i + 3] = a.w * b.w;
        }
    }
    __syncthreads();

    // Phase 2: dual consecutive edges 2t, 2t+1; weights from constant.
    float* x0 = xs + tid * XSTRIDE;
    float* x1 = xs + (tid + 128) * XSTRIDE;

    {
        u64 a0[24], a1[24];
        gemm48_dual_c(x0, x1, a0, a1, c_mw, 0, 4608);
        relu_writeback(x0, a0);
        relu_writeback(x1, a1);
    }

    u64 a0[24], a1[24];
    gemm48_dual_c(x0, x1, a0, a1, c_mw, 2304, 4656);

    int dst0 = edst[2 * tid];
    int dst1 = edst[2 * tid + 1];
    if (dst0 == dst1) {
#pragma unroll
        for (int j = 0; j < 24; j++) a0[j] = add2(a0[j], a1[j]);
        scatter48((float*)&g_agg[dst0 * 12], a0);
    } else {
        scatter48((float*)&g_agg[dst0 * 12], a0);
        scatter48((float*)&g_agg[dst1 * 12], a1);
    }
}

// Dual-node update kernel: constant weights, x staged in smem.
__global__ __launch_bounds__(128, 3) void update_kernel(int unused) {
    extern __shared__ __align__(16) float s[];
    float* xs = s;
    int tid = threadIdx.x;

    int n_base = blockIdx.x * 256;
    const float4 z = make_float4(0.f, 0.f, 0.f, 0.f);
#pragma unroll
    for (int it = 0; it < 8; it++) {
        int idx = it * 128 + tid;
        int nl = idx >> 2;
        int ch = idx & 3;
        int n = n_base + nl;
        if (n < NN) {
            float4* ap = &g_agg[n * 12] + ch * 3;
            int row = ((nl & 1) << 7) + (nl >> 1);
            float* xrow = xs + row * XSTRIDE + ch * 12;
#pragma unroll
            for (int i = 0; i < 3; i++) {
                float4 a = ap[i];
                xrow[4 * i + 0] = a.x;
                xrow[4 * i + 1] = a.y;
                xrow[4 * i + 2] = a.z;
                xrow[4 * i + 3] = a.w;
                ap[i] = z;  // reset for next layer's scatter
            }
        }
    }
    __syncthreads();

    int n0 = n_base + 2 * tid;
    if (n0 >= NN) return;
    int n1 = n0 + 1;

    float* x0 = xs + tid * XSTRIDE;
    float* x1 = xs + (tid + 128) * XSTRIDE;

    {
        u64 a0[24], a1[24];
        gemm48_dual_c(x0, x1, a0, a1, c_uw, 0, 4608);
        relu_writeback(x0, a0);
        relu_writeback(x1, a1);
    }

    u64 a0[24], a1[24];
    gemm48_dual_c(x0, x1, a0, a1, c_uw, 2304, 4656);

    {
        float4* hp = &g_h[n0 * 12];
#pragma unroll
        for (int v = 0; v < 12; v++) {
            float2 p0 = unpack2(a0[2 * v]);
            float2 p1 = unpack2(a0[2 * v + 1]);
            float4 h = hp[v];
            h.x += p0.x; h.y += p0.y; h.z += p1.x; h.w += p1.y;
            hp[v] = h;
        }
    }
    if (n1 < NN) {
        float4* hp = &g_h[n1 * 12];
#pragma unroll
        for (int v = 0; v < 12; v++) {
            float2 p0 = unpack2(a1[2 * v]);
            float2 p1 = unpack2(a1[2 * v + 1]);
            float4 h = hp[v];
            h.x += p0.x; h.y += p0.y; h.z += p1.x; h.w += p1.y;
            hp[v] = h;
        }
    }
}

__global__ __launch_bounds__(256, 2) void readout_kernel(
    const int* __restrict__ gid,
    const float* __restrict__ rw1, const float* __restrict__ rb1,
    const float* __restrict__ rw2, const float* __restrict__ rb2,
    float* __restrict__ out) {
    __shared__ __align__(16) float s[2402];
    for (int i = threadIdx.x; i < D * D; i += blockDim.x) s[i] = rw1[i];
    if (threadIdx.x < D) {
        s[2304 + threadIdx.x] = rb1[threadIdx.x];
        s[2352 + threadIdx.x] = rw2[threadIdx.x];
    }
    if (threadIdx.x == 0) s[2400] = rb2[0];
    __syncthreads();

    int n = blockIdx.x * 256 + threadIdx.x;
    if (n >= NN) return;

    const float4* hp = &g_h[n * 12];
    float x[D];
#pragma unroll
    for (int v = 0; v < 12; v++) {
        float4 a = hp[v];
        x[4 * v + 0] = a.x;
        x[4 * v + 1] = a.y;
        x[4 * v + 2] = a.z;
        x[4 * v + 3] = a.w;
    }

    float y = s[2400];
#pragma unroll 1
    for (int half = 0; half < 2; half++) {
        u64 acc[12];
        gemm48_half(x, acc, s + half * 24, s + 2304 + half * 24);
#pragma unroll
        for (int j = 0; j < 12; j++) {
            float2 v = unpack2(acc[j]);
            y += fmaxf(v.x, 0.f) * s[2352 + half * 24 + 2 * j];
            y += fmaxf(v.y, 0.f) * s[2352 + half * 24 + 2 * j + 1];
        }
    }

    atomicAdd(&out[gid[n]], y);
}

extern "C" void kernel_launch(void* const* d_in, const int* in_sizes, int n_in,
                              void* d_out, int out_size) {
    const int*   an   = (const int*)d_in[0];
    const int*   edge = (const int*)d_in[1];
    const int*   gid  = (const int*)d_in[2];
    const float* emb  = (const float*)d_in[3];
    const float* mw1  = (const float*)d_in[4];
    const float* mb1  = (const float*)d_in[5];
    const float* mw2  = (const float*)d_in[6];
    const float* mb2  = (const float*)d_in[7];
    const float* uw1  = (const float*)d_in[8];
    const float* ub1  = (const float*)d_in[9];
    const float* uw2  = (const float*)d_in[10];
    const float* ub2  = (const float*)d_in[11];
    const float* rw1  = (const float*)d_in[12];
    const float* rb1  = (const float*)d_in[13];
    const float* rw2  = (const float*)d_in[14];
    const float* rb2  = (const float*)d_in[15];
    float* out = (float*)d_out;

    const int edge_smem = EDGE_SMEM_FLOATS * (int)sizeof(float);  // ~52 KB
    const int upd_smem  = UPD_SMEM_FLOATS * (int)sizeof(float);   // ~50 KB
    cudaFuncSetAttribute(edge_kernel, cudaFuncAttributeMaxDynamicSharedMemorySize, edge_smem);
    cudaFuncSetAttribute(update_kernel, cudaFuncAttributeMaxDynamicSharedMemorySize, upd_smem);

    // Host-side device addresses of staging/constant symbols (no-work queries).
    void *pm = nullptr, *pu = nullptr;
    cudaGetSymbolAddress(&pm, g_packm);
    cudaGetSymbolAddress(&pu, g_packu);

    // Pack all layers' weights contiguously (one kernel, replaces 36 memcpy nodes).
    pack_weights_kernel<<<(NCONVS * 4704 + 255) / 256, 256>>>(mw1, mb1, mw2, mb2,
                                                              uw1, ub1, uw2, ub2);

    // counting sort of edges by dst (edge list constant across layers)
    zero_cnt_kernel<<<(NN + 255) / 256, 256>>>();
    hist_kernel<<<(NE + 255) / 256, 256>>>(edge);
    scan1_kernel<<<NSCAN_BLKS, SCAN_BLK>>>();
    scan2_kernel<<<1, 32>>>();
    scan3_kernel<<<(NN + 255) / 256, 256>>>();
    scatter_sort_kernel<<<(NE + 255) / 256, 256>>>(edge);

    embed_kernel<<<(NN * 12 + 255) / 256, 256>>>(an, (const float4*)emb);

    for (int l = 0; l < NCONVS; l++) {
        cudaMemcpyToSymbolAsync(c_mw, (const float*)pm + l * 4704, 4704 * sizeof(float), 0,
                                cudaMemcpyDeviceToDevice);
        edge_kernel<<<NE / EPC, 128, edge_smem>>>(0);

        cudaMemcpyToSymbolAsync(c_uw, (const float*)pu + l * 4704, 4704 * sizeof(float), 0,
                                cudaMemcpyDeviceToDevice);
        update_kernel<<<(NN + 255) / 256, 128, upd_smem>>>(0);
    }

    cudaMemsetAsync(out, 0, NG * sizeof(float));
    readout_kernel<<<(NN + 255) / 256, 256>>>(gid, rw1, rb1, rw2, rb2, out);
}